// round 3
// baseline (speedup 1.0000x reference)
#include <cuda_runtime.h>
#include <math.h>

#define NA 120            // angles
#define LL 91             // padded canvas size / detector bins
#define NS 64             // slices
#define PADW 66           // 64 + 1 zero border on each side
#define NRAYS (NA * LL)   // 10920

// Zero-padded transposed diff volume: g_dT[dp][wp][s], dp/wp in [0,65],
// border (dp==0||65, wp==0||65) stays zero -> no bounds checks on bilinear taps.
__device__ float g_dT[PADW * PADW * NS];
// One partial per ray (a, j): sum over slices of |line integral|.
__device__ float g_partials[NRAYS];

// Kernel 1: diff + transpose into padded layout.
// Input volumes are [D=64][H=64][W=64] with slice s = vol[d][s][w].
// Output g_dT[(dp*PADW + wp)*NS + s] = out[d][s][w] - gt[d][s][w], d=dp-1, w=wp-1.
__global__ void k_diff(const float* __restrict__ a,
                       const float* __restrict__ b) {
    int idx = blockIdx.x * blockDim.x + threadIdx.x;
    if (idx >= PADW * PADW * NS) return;
    int s  = idx & (NS - 1);
    int t  = idx >> 6;
    int wp = t % PADW;
    int dp = t / PADW;
    float v = 0.0f;
    if (dp >= 1 && dp <= 64 && wp >= 1 && wp <= 64) {
        int d = dp - 1, w = wp - 1;
        int o = (d * 64 + s) * 64 + w;
        v = a[o] - b[o];
    }
    g_dT[idx] = v;
}

// Kernel 2: one CTA per ray (angle a, detector bin j); thread = slice s.
// Line integral: sum over i of bilinear sample of diff image at
//   ix = c*(j-45) - s*(i-45) + 32   (column / w coordinate)
//   iy = s*(j-45) + c*(i-45) + 32   (row    / d coordinate)
// Outside (-1, 64) in either coord the 2x2 footprint is all-zero -> skip.
__global__ void __launch_bounds__(NS) k_radon() {
    int blk = blockIdx.x;
    int a   = blk / LL;
    int j   = blk - a * LL;
    int s   = threadIdx.x;

    // theta = a * (120/119) degrees, matching jnp.linspace(0,120,120)*pi/180
    float theta = (float)a * (float)(120.0 / 119.0 * 3.14159265358979323846 / 180.0);
    float cth, sth;
    sincosf(theta, &sth, &cth);

    float uj = (float)(j - 45);
    float bx = fmaf(cth, uj, 32.0f);
    float by = fmaf(sth, uj, 32.0f);

    float acc = 0.0f;
    #pragma unroll 1
    for (int i = 0; i < LL; ++i) {
        float vi = (float)(i - 45);
        float ix = fmaf(-sth, vi, bx);
        float iy = fmaf( cth, vi, by);
        // Uniform across the block -> no divergence, cheap skip of ~51% of samples.
        if (ix <= -1.0f || ix >= 64.0f || iy <= -1.0f || iy >= 64.0f) continue;

        float fw = floorf(ix), fd = floorf(iy);
        int   w0 = (int)fw,    d0 = (int)fd;      // in [-1, 63]
        float fx = ix - fw,    fy = iy - fd;

        // Padded index: rows d0+1..d0+2 in [0,64], cols w0+1..w0+2 in [0,64].
        const float* p = g_dT + ((d0 + 1) * PADW + (w0 + 1)) * NS + s;
        float v00 = p[0];
        float v01 = p[NS];
        float v10 = p[PADW * NS];
        float v11 = p[PADW * NS + NS];

        float top = fmaf(fx, v01 - v00, v00);
        float bot = fmaf(fx, v11 - v10, v10);
        acc += fmaf(fy, bot - top, top);
    }

    // Sum |acc| over the 64 slices of this block.
    float val = fabsf(acc);
    #pragma unroll
    for (int off = 16; off; off >>= 1)
        val += __shfl_down_sync(0xffffffffu, val, off);

    __shared__ float sh[2];
    if ((threadIdx.x & 31) == 0) sh[threadIdx.x >> 5] = val;
    __syncthreads();
    if (threadIdx.x == 0) g_partials[blk] = sh[0] + sh[1];
}

// Kernel 3: deterministic fixed-order reduction of the 10920 ray partials,
// accumulated in double, scaled by 1/(NA*LL) (per-slice mean over (A,L),
// summed over slices).
__global__ void k_reduce(float* __restrict__ d_out) {
    __shared__ double sh[256];
    double t = 0.0;
    for (int k = threadIdx.x; k < NRAYS; k += 256)
        t += (double)g_partials[k];
    sh[threadIdx.x] = t;
    __syncthreads();
    #pragma unroll
    for (int st = 128; st; st >>= 1) {
        if (threadIdx.x < st) sh[threadIdx.x] += sh[threadIdx.x + st];
        __syncthreads();
    }
    if (threadIdx.x == 0)
        d_out[0] = (float)(sh[0] * (1.0 / (double)(NA * LL)));
}

extern "C" void kernel_launch(void* const* d_in, const int* in_sizes, int n_in,
                              void* d_out, int out_size) {
    const float* v_out = (const float*)d_in[0];
    const float* v_gt  = (const float*)d_in[1];
    // (order doesn't matter: the loss is symmetric in the two volumes)

    int n_pad = PADW * PADW * NS;
    k_diff<<<(n_pad + 255) / 256, 256>>>(v_out, v_gt);
    k_radon<<<NRAYS, NS>>>();
    k_reduce<<<1, 256>>>((float*)d_out);
}

// round 4
// speedup vs baseline: 1.1869x; 1.1869x over previous
#include <cuda_runtime.h>
#include <math.h>

#define NA 120            // angles
#define LL 91             // padded canvas size / detector bins
#define NS 64             // slices
#define PADW 66           // 64 + 1 zero border each side (scalar diff array)
#define QW 65             // quad-tap array extent per axis (dp,wp in [0,64])
#define NRAYS (NA * LL)   // 10920

// Zero-padded transposed diff volume: g_dT[dp][wp][s]; borders stay zero
// (zero-initialized at module load, never written).
__device__ float g_dT[PADW * PADW * NS];
// Quad-tap array: g_q[dp][wp][s] = (v[dp][wp], v[dp][wp+1], v[dp+1][wp], v[dp+1][wp+1])
__device__ float4 g_q[QW * QW * NS];
// One partial per ray (a, j): sum over slices of |line integral|.
__device__ float g_partials[NRAYS];

// Kernel 1: diff + transpose, smem-staged for full coalescing on both sides.
// One block per d-plane. Input plane a[d][s][w]; output g_dT[(d+1,w+1)][s].
__global__ void __launch_bounds__(256) k_diffT(const float* __restrict__ a,
                                               const float* __restrict__ b) {
    __shared__ float tile[64][65];   // [s][w], stride 65 -> conflict-free column reads
    int d = blockIdx.x;
    const float* pa = a + d * 4096;
    const float* pb = b + d * 4096;
    for (int k = threadIdx.x; k < 4096; k += 256) {   // k = s*64 + w, w fast -> coalesced
        tile[k >> 6][k & 63] = pa[k] - pb[k];
    }
    __syncthreads();
    for (int k = threadIdx.x; k < 4096; k += 256) {   // k = w*64 + s, s fast -> coalesced
        int w = k >> 6, s = k & 63;
        g_dT[((d + 1) * PADW + (w + 1)) * NS + s] = tile[s][w];
    }
}

// Kernel 2: gather the 2x2 bilinear footprint into float4 (all accesses coalesced).
__global__ void __launch_bounds__(256) k_build4() {
    int idx = blockIdx.x * blockDim.x + threadIdx.x;
    if (idx >= QW * QW * NS) return;
    int s  = idx & (NS - 1);
    int t  = idx >> 6;
    int wp = t % QW;
    int dp = t / QW;
    const float* base = g_dT + (dp * PADW + wp) * NS + s;
    float4 q;
    q.x = base[0];
    q.y = base[NS];
    q.z = base[PADW * NS];
    q.w = base[PADW * NS + NS];
    g_q[idx] = q;
}

// Kernel 3: 4 rays per 256-thread CTA; thread group of 64 = slices of one ray.
//   ix(i) = Cx - sth*i,  iy(i) = Cy + cth*i   (linear in i -> analytic range)
__global__ void __launch_bounds__(256) k_radon() {
    int tid = threadIdx.x;
    int s   = tid & 63;
    int sub = tid >> 6;                 // ray-within-block (0..3)
    int ray = blockIdx.x * 4 + sub;     // NRAYS = 10920 = 2730 * 4 exactly
    int a   = ray / LL;
    int j   = ray - a * LL;

    // theta = a * (120/119) degrees (jnp.linspace(0,120,120) * pi/180)
    float theta = (float)a * (float)(120.0 / 119.0 * 3.14159265358979323846 / 180.0);
    float cth, sth;
    sincosf(theta, &sth, &cth);

    float uj = (float)(j - 45);
    float Cx = fmaf(cth, uj, 32.0f) + 45.0f * sth;   // ix = Cx - sth*i
    float Cy = fmaf(sth, uj, 32.0f) - 45.0f * cth;   // iy = Cy + cth*i

    // Analytic active range (widened by 1; strict guard kept in-loop).
    int ilo = 0, ihi = LL;
    {
        float D = -sth, C = Cx;
        if (fabsf(D) > 1e-6f) {
            float r1 = (-1.0f - C) / D, r2 = (64.0f - C) / D;
            float lo = fminf(r1, r2), hi = fmaxf(r1, r2);
            ilo = max(ilo, (int)ceilf(lo) - 1);
            ihi = min(ihi, (int)floorf(hi) + 2);
        } else if (C <= -1.0f || C >= 64.0f) {
            ihi = ilo;
        }
    }
    {
        float D = cth, C = Cy;
        if (fabsf(D) > 1e-6f) {
            float r1 = (-1.0f - C) / D, r2 = (64.0f - C) / D;
            float lo = fminf(r1, r2), hi = fmaxf(r1, r2);
            ilo = max(ilo, (int)ceilf(lo) - 1);
            ihi = min(ihi, (int)floorf(hi) + 2);
        } else if (C <= -1.0f || C >= 64.0f) {
            ihi = ilo;
        }
    }
    ilo = max(ilo, 0);
    ihi = min(ihi, LL);

    float acc = 0.0f;
    #pragma unroll 2
    for (int i = ilo; i < ihi; ++i) {
        float fi = (float)i;
        float ix = fmaf(-sth, fi, Cx);
        float iy = fmaf( cth, fi, Cy);
        if (ix > -1.0f && ix < 64.0f && iy > -1.0f && iy < 64.0f) {
            float fw = floorf(ix), fd = floorf(iy);
            int   w0 = (int)fw,    d0 = (int)fd;    // in [-1, 63]
            float fx = ix - fw,    fy = iy - fd;
            float4 v = g_q[((d0 + 1) * QW + (w0 + 1)) * NS + s];
            float top = fmaf(fx, v.y - v.x, v.x);
            float bot = fmaf(fx, v.w - v.z, v.z);
            acc += fmaf(fy, bot - top, top);
        }
    }

    // Reduce |acc| over each 64-thread ray group.
    float val = fabsf(acc);
    #pragma unroll
    for (int off = 16; off; off >>= 1)
        val += __shfl_down_sync(0xffffffffu, val, off);

    __shared__ float sh[8];
    if ((tid & 31) == 0) sh[tid >> 5] = val;
    __syncthreads();
    if ((tid & 63) == 0)
        g_partials[ray] = sh[sub * 2] + sh[sub * 2 + 1];
}

// Kernel 4: deterministic fixed-order reduction (double accumulation),
// scaled by 1/(NA*LL): per-slice mean over (A,L), summed over slices.
__global__ void k_reduce(float* __restrict__ d_out) {
    __shared__ double sh[256];
    double t = 0.0;
    for (int k = threadIdx.x; k < NRAYS; k += 256)
        t += (double)g_partials[k];
    sh[threadIdx.x] = t;
    __syncthreads();
    #pragma unroll
    for (int st = 128; st; st >>= 1) {
        if (threadIdx.x < st) sh[threadIdx.x] += sh[threadIdx.x + st];
        __syncthreads();
    }
    if (threadIdx.x == 0)
        d_out[0] = (float)(sh[0] * (1.0 / (double)(NA * LL)));
}

extern "C" void kernel_launch(void* const* d_in, const int* in_sizes, int n_in,
                              void* d_out, int out_size) {
    const float* v_out = (const float*)d_in[0];
    const float* v_gt  = (const float*)d_in[1];

    k_diffT<<<64, 256>>>(v_out, v_gt);
    int nq = QW * QW * NS;
    k_build4<<<(nq + 255) / 256, 256>>>();
    k_radon<<<NRAYS / 4, 256>>>();
    k_reduce<<<1, 256>>>((float*)d_out);
}

// round 6
// speedup vs baseline: 1.4101x; 1.1881x over previous
#include <cuda_runtime.h>
#include <math.h>

#define NA 120            // angles
#define LL 91             // padded canvas size / detector bins
#define NS 64             // slices
#define QW 65             // quad-tap array extent per axis (dp,wp in [0,64])
#define NRAYS (NA * LL)   // 10920
#define NBLK  (NRAYS / 4) // 2730 k_radon CTAs
#define SCALE 4294967296.0   // 2^32 fixed-point scale

// Quad-tap array: g_q[dp][wp][s] = (v[dp][wp], v[dp][wp+1], v[dp+1][wp], v[dp+1][wp+1])
// where v is the zero-padded transposed diff image (v[r][c] = diff(r-1, c-1)).
__device__ float4 g_q[QW * QW * NS];
// Fixed-point global accumulator + completion ticket (zero-initialized at load;
// the last k_radon CTA resets them each call, so graph replays stay correct).
__device__ unsigned long long g_total;
__device__ unsigned int g_done;

// Kernel 1: fused diff + transpose + quad-tap build. One CTA per dp in [0,64].
// Needs diff planes d = dp-1 and dp (zero outside [0,63]).
__global__ void __launch_bounds__(256) k_build(const float* __restrict__ a,
                                               const float* __restrict__ b) {
    // tile[p][s][c]: p = plane (dp-1+p), c = padded column (w+1), width 67 for
    // conflict-free strided reads; columns 0 and 65 stay zero.
    __shared__ float tile[2][64][67];
    int dp = blockIdx.x;

    for (int k = threadIdx.x; k < 2 * 64 * 67; k += 256)
        ((float*)tile)[k] = 0.0f;
    __syncthreads();

    #pragma unroll
    for (int p = 0; p < 2; ++p) {
        int d = dp - 1 + p;
        if (d >= 0 && d < 64) {
            const float* pa = a + d * 4096;
            const float* pb = b + d * 4096;
            for (int k = threadIdx.x; k < 4096; k += 256)   // k = s*64 + w, coalesced
                tile[p][k >> 6][(k & 63) + 1] = pa[k] - pb[k];
        }
    }
    __syncthreads();

    // Write g_q[dp][wp][s] for wp in [0,64], s in [0,63]; float4 writes coalesced.
    for (int k = threadIdx.x; k < QW * NS; k += 256) {      // k = wp*64 + s
        int wp = k >> 6, s = k & 63;
        float4 q;
        q.x = tile[0][s][wp];       // v[dp  ][wp  ]
        q.y = tile[0][s][wp + 1];   // v[dp  ][wp+1]
        q.z = tile[1][s][wp];       // v[dp+1][wp  ]
        q.w = tile[1][s][wp + 1];   // v[dp+1][wp+1]
        g_q[(dp * QW + wp) * NS + s] = q;
    }
}

// Kernel 2: 4 rays per 256-thread CTA; 64-thread group = slices of one ray.
//   ix(i) = Cx - sth*i,  iy(i) = Cy + cth*i   (linear in i -> analytic range)
// CTA partial -> 2^32 fixed-point integer atomicAdd (deterministic); the last
// CTA writes the scalar and resets state.
__global__ void __launch_bounds__(256) k_radon(float* __restrict__ d_out) {
    int tid = threadIdx.x;
    int s   = tid & 63;
    int sub = tid >> 6;                 // ray-within-block (0..3)
    int ray = blockIdx.x * 4 + sub;
    int a   = ray / LL;
    int j   = ray - a * LL;

    // theta = a * (120/119) degrees (jnp.linspace(0,120,120) * pi/180)
    float theta = (float)a * (float)(120.0 / 119.0 * 3.14159265358979323846 / 180.0);
    float cth, sth;
    sincosf(theta, &sth, &cth);

    float uj = (float)(j - 45);
    float Cx = fmaf(cth, uj, 32.0f) + 45.0f * sth;   // ix = Cx - sth*i
    float Cy = fmaf(sth, uj, 32.0f) - 45.0f * cth;   // iy = Cy + cth*i

    // Analytic active range (widened by 1; strict guard kept in-loop).
    int ilo = 0, ihi = LL;
    {
        float D = -sth, C = Cx;
        if (fabsf(D) > 1e-6f) {
            float r1 = (-1.0f - C) / D, r2 = (64.0f - C) / D;
            float lo = fminf(r1, r2), hi = fmaxf(r1, r2);
            ilo = max(ilo, (int)ceilf(lo) - 1);
            ihi = min(ihi, (int)floorf(hi) + 2);
        } else if (C <= -1.0f || C >= 64.0f) {
            ihi = ilo;
        }
    }
    {
        float D = cth, C = Cy;
        if (fabsf(D) > 1e-6f) {
            float r1 = (-1.0f - C) / D, r2 = (64.0f - C) / D;
            float lo = fminf(r1, r2), hi = fmaxf(r1, r2);
            ilo = max(ilo, (int)ceilf(lo) - 1);
            ihi = min(ihi, (int)floorf(hi) + 2);
        } else if (C <= -1.0f || C >= 64.0f) {
            ihi = ilo;
        }
    }
    ilo = max(ilo, 0);
    ihi = min(ihi, LL);

    float acc = 0.0f;
    #pragma unroll 4
    for (int i = ilo; i < ihi; ++i) {
        float fi = (float)i;
        float ix = fmaf(-sth, fi, Cx);
        float iy = fmaf( cth, fi, Cy);
        if (ix > -1.0f && ix < 64.0f && iy > -1.0f && iy < 64.0f) {
            float fw = floorf(ix), fd = floorf(iy);
            int   w0 = (int)fw,    d0 = (int)fd;    // in [-1, 63]
            float fx = ix - fw,    fy = iy - fd;
            float4 v = g_q[((d0 + 1) * QW + (w0 + 1)) * NS + s];
            float top = fmaf(fx, v.y - v.x, v.x);
            float bot = fmaf(fx, v.w - v.z, v.z);
            acc += fmaf(fy, bot - top, top);
        }
    }

    // Reduce |acc| within each 64-thread ray group, then across the CTA.
    float val = fabsf(acc);
    #pragma unroll
    for (int off = 16; off; off >>= 1)
        val += __shfl_down_sync(0xffffffffu, val, off);

    __shared__ float sh[8];
    if ((tid & 31) == 0) sh[tid >> 5] = val;
    __syncthreads();

    if (tid == 0) {
        // Fixed-order double sum of the 8 warp partials -> fixed point.
        double tot = 0.0;
        #pragma unroll
        for (int k = 0; k < 8; ++k) tot += (double)sh[k];
        unsigned long long q = (unsigned long long)(tot * SCALE);
        atomicAdd(&g_total, q);
        __threadfence();
        unsigned int old = atomicAdd(&g_done, 1u);
        if (old == NBLK - 1) {
            unsigned long long total = atomicAdd(&g_total, 0ULL);  // fenced read
            d_out[0] = (float)((double)total * (1.0 / SCALE) / (double)NRAYS);
            // Reset for the next (graph-replayed) call.
            g_total = 0ULL;
            g_done  = 0u;
        }
    }
}

extern "C" void kernel_launch(void* const* d_in, const int* in_sizes, int n_in,
                              void* d_out, int out_size) {
    const float* v_out = (const float*)d_in[0];
    const float* v_gt  = (const float*)d_in[1];

    k_build<<<QW, 256>>>(v_out, v_gt);
    k_radon<<<NBLK, 256>>>((float*)d_out);
}

// round 9
// speedup vs baseline: 1.6555x; 1.1740x over previous
#include <cuda_runtime.h>
#include <math.h>

#define NA 120            // angles
#define LL 91             // padded canvas size / detector bins
#define NS 64             // slices
#define QW 65             // quad-tap array extent per axis (dp,wp in [0,64])
#define NRAYS (NA * LL)   // 10920
#define RPB 4             // rays per CTA
#define NBLK  (NRAYS / RPB)
#define SCALE 4294967296.0   // 2^32 fixed-point scale

// Quad-tap array: g_q[dp][wp][s] = (v[dp][wp], v[dp][wp+1], v[dp+1][wp], v[dp+1][wp+1])
// where v is the zero-padded transposed diff image (v[r][c] = diff(r-1, c-1)).
__device__ float4 g_q[QW * QW * NS];
// Fixed-point global accumulator + completion ticket (zero-initialized at load;
// the last k_radon CTA resets them, so graph replays stay correct).
__device__ unsigned long long g_total;
__device__ unsigned int g_done;

// Kernel 1: fused diff + transpose + quad-tap build. One CTA per dp in [0,64].
__global__ void __launch_bounds__(256) k_build(const float* __restrict__ a,
                                               const float* __restrict__ b) {
    __shared__ float tile[2][64][67];   // [plane][s][padded col]; cols 0,65 zero
    int dp = blockIdx.x;

    for (int k = threadIdx.x; k < 2 * 64 * 67; k += 256)
        ((float*)tile)[k] = 0.0f;
    __syncthreads();

    #pragma unroll
    for (int p = 0; p < 2; ++p) {
        int d = dp - 1 + p;
        if (d >= 0 && d < 64) {
            const float* pa = a + d * 4096;
            const float* pb = b + d * 4096;
            for (int k = threadIdx.x; k < 4096; k += 256)   // k = s*64 + w, coalesced
                tile[p][k >> 6][(k & 63) + 1] = pa[k] - pb[k];
        }
    }
    __syncthreads();

    for (int k = threadIdx.x; k < QW * NS; k += 256) {      // k = wp*64 + s
        int wp = k >> 6, s = k & 63;
        float4 q;
        q.x = tile[0][s][wp];
        q.y = tile[0][s][wp + 1];
        q.z = tile[1][s][wp];
        q.w = tile[1][s][wp + 1];
        g_q[(dp * QW + wp) * NS + s] = q;
    }
}

// Kernel 2: 4 rays per CTA. Phase 0/1 cooperatively precompute per-sample
// (byte offset, 4 corner weights) into smem; phase 2 is a branch-free
// LDS + LDG.128 + 4-FMA inner loop per slice.
__global__ void __launch_bounds__(256) k_radon(float* __restrict__ d_out) {
    __shared__ float4 s_w[RPB][92];   // corner weights (w00,w01,w10,w11)
    __shared__ int    s_o[RPB][92];   // byte offset into g_q (row base)
    __shared__ float  s_prm[RPB][4];  // sth, cth, Cx, Cy
    __shared__ int    s_ilo[RPB], s_cnt[RPB];
    __shared__ float  s_red[8];

    int tid = threadIdx.x;

    // ---- Phase 0: per-ray params + analytic active range (4 threads) ----
    if (tid < RPB) {
        int ray = blockIdx.x * RPB + tid;
        int a   = ray / LL;
        int j   = ray - a * LL;
        float theta = (float)a * (float)(120.0 / 119.0 * 3.14159265358979323846 / 180.0);
        float cth, sth;
        sincosf(theta, &sth, &cth);
        float uj = (float)(j - 45);
        float Cx = fmaf(cth, uj, 32.0f) + 45.0f * sth;   // ix = Cx - sth*i
        float Cy = fmaf(sth, uj, 32.0f) - 45.0f * cth;   // iy = Cy + cth*i

        int ilo = 0, ihi = LL;
        {
            float D = -sth, C = Cx;
            if (fabsf(D) > 1e-6f) {
                float r1 = (-1.0f - C) / D, r2 = (64.0f - C) / D;
                float lo = fminf(r1, r2), hi = fmaxf(r1, r2);
                ilo = max(ilo, (int)ceilf(lo) - 1);
                ihi = min(ihi, (int)floorf(hi) + 2);
            } else if (C <= -1.0f || C >= 64.0f) ihi = ilo;
        }
        {
            float D = cth, C = Cy;
            if (fabsf(D) > 1e-6f) {
                float r1 = (-1.0f - C) / D, r2 = (64.0f - C) / D;
                float lo = fminf(r1, r2), hi = fmaxf(r1, r2);
                ilo = max(ilo, (int)ceilf(lo) - 1);
                ihi = min(ihi, (int)floorf(hi) + 2);
            } else if (C <= -1.0f || C >= 64.0f) ihi = ilo;
        }
        ilo = max(ilo, 0);
        ihi = min(ihi, LL);
        s_prm[tid][0] = sth; s_prm[tid][1] = cth;
        s_prm[tid][2] = Cx;  s_prm[tid][3] = Cy;
        s_ilo[tid] = ilo;
        s_cnt[tid] = max(ihi - ilo, 0);
    }
    __syncthreads();

    // ---- Phase 1: per-sample offsets + weights (cooperative, 4*91 entries) ----
    for (int t = tid; t < RPB * LL; t += 256) {
        int sub = t / LL;
        int ir  = t - sub * LL;
        if (ir < s_cnt[sub]) {
            int i = s_ilo[sub] + ir;
            float sth = s_prm[sub][0], cth = s_prm[sub][1];
            float Cx  = s_prm[sub][2], Cy  = s_prm[sub][3];
            float fi = (float)i;
            float ix = fmaf(-sth, fi, Cx);
            float iy = fmaf( cth, fi, Cy);
            float4 w = make_float4(0.f, 0.f, 0.f, 0.f);
            int off = 0;
            if (ix > -1.0f && ix < 64.0f && iy > -1.0f && iy < 64.0f) {
                float fw = floorf(ix), fd = floorf(iy);
                int   w0 = (int)fw,    d0 = (int)fd;    // in [-1, 63]
                float fx = ix - fw,    fy = iy - fd;
                float w11 = fx * fy;
                w.x = 1.0f - fx - fy + w11;   // (1-fx)(1-fy) -> v[dp][wp]
                w.y = fx - w11;               // fx(1-fy)     -> v[dp][wp+1]
                w.z = fy - w11;               // fy(1-fx)     -> v[dp+1][wp]
                w.w = w11;                    // fx*fy        -> v[dp+1][wp+1]
                off = ((d0 + 1) * QW + (w0 + 1)) * (NS * 16);  // byte offset
            }
            s_w[sub][ir] = w;
            s_o[sub][ir] = off;
        }
    }
    __syncthreads();

    // ---- Phase 2: lean accumulate. 64 threads = slices of one ray. ----
    int s   = tid & 63;
    int sub = tid >> 6;
    int cnt = s_cnt[sub];
    const char* gq = (const char*)g_q + s * 16;

    float acc0 = 0.0f, acc1 = 0.0f;
    #pragma unroll 2
    for (int k = 0; k < cnt; ++k) {
        float4 w = s_w[sub][k];                 // LDS.128 broadcast
        int off  = s_o[sub][k];
        float4 v = *(const float4*)(gq + off);  // LDG.128 coalesced
        acc0 = fmaf(w.x, v.x, acc0);
        acc0 = fmaf(w.y, v.y, acc0);
        acc1 = fmaf(w.z, v.z, acc1);
        acc1 = fmaf(w.w, v.w, acc1);
    }

    // Reduce |acc| within each 64-thread ray group, then across the CTA.
    float val = fabsf(acc0 + acc1);
    #pragma unroll
    for (int off = 16; off; off >>= 1)
        val += __shfl_down_sync(0xffffffffu, val, off);

    if ((tid & 31) == 0) s_red[tid >> 5] = val;
    __syncthreads();

    if (tid == 0) {
        double tot = 0.0;
        #pragma unroll
        for (int k = 0; k < 8; ++k) tot += (double)s_red[k];
        unsigned long long q = (unsigned long long)(tot * SCALE);
        atomicAdd(&g_total, q);
        __threadfence();
        unsigned int old = atomicAdd(&g_done, 1u);
        if (old == NBLK - 1) {
            unsigned long long total = atomicAdd(&g_total, 0ULL);  // fenced read
            d_out[0] = (float)((double)total * (1.0 / SCALE) / (double)NRAYS);
            g_total = 0ULL;   // reset for next graph replay
            g_done  = 0u;
        }
    }
}

extern "C" void kernel_launch(void* const* d_in, const int* in_sizes, int n_in,
                              void* d_out, int out_size) {
    const float* v_out = (const float*)d_in[0];
    const float* v_gt  = (const float*)d_in[1];

    k_build<<<QW, 256>>>(v_out, v_gt);
    k_radon<<<NBLK, 256>>>((float*)d_out);
}

// round 14
// speedup vs baseline: 2.1209x; 1.2811x over previous
#include <cuda_runtime.h>
#include <cuda_fp16.h>
#include <math.h>

#define NA 120            // angles
#define LL 91             // padded canvas size / detector bins
#define NS 64             // slices
#define QW 65             // quad-tap array extent per axis (dp,wp in [0,64])
#define NRAYS (NA * LL)   // 10920
#define RPB 4             // rays per CTA
#define NBLK  (NRAYS / RPB)
#define SCALE 4294967296.0   // 2^32 fixed-point scale

// Quad-tap array in fp16: g_qh[(dp*QW+wp)*NS+s] = half4(v[dp][wp], v[dp][wp+1],
// v[dp+1][wp], v[dp+1][wp+1]) packed as uint2 (8 bytes), where v is the
// zero-padded transposed diff image (v[r][c] = diff(r-1, c-1)).
__device__ uint2 g_qh[QW * QW * NS];
// Fixed-point global accumulator + completion ticket (zero-initialized at load;
// the last k_radon CTA resets them, so graph replays stay correct).
__device__ unsigned long long g_total;
__device__ unsigned int g_done;

// Kernel 1: fused diff + transpose + quad-tap build (fp16 output).
// One CTA per dp in [0,64].
__global__ void __launch_bounds__(256) k_build(const float* __restrict__ a,
                                               const float* __restrict__ b) {
    __shared__ float tile[2][64][67];   // [plane][s][padded col]; cols 0,65 zero
    int dp = blockIdx.x;

    for (int k = threadIdx.x; k < 2 * 64 * 67; k += 256)
        ((float*)tile)[k] = 0.0f;
    __syncthreads();

    #pragma unroll
    for (int p = 0; p < 2; ++p) {
        int d = dp - 1 + p;
        if (d >= 0 && d < 64) {
            const float* pa = a + d * 4096;
            const float* pb = b + d * 4096;
            for (int k = threadIdx.x; k < 4096; k += 256)   // k = s*64 + w, coalesced
                tile[p][k >> 6][(k & 63) + 1] = pa[k] - pb[k];
        }
    }
    __syncthreads();

    for (int k = threadIdx.x; k < QW * NS; k += 256) {      // k = wp*64 + s
        int wp = k >> 6, s = k & 63;
        __half2 lo = __floats2half2_rn(tile[0][s][wp], tile[0][s][wp + 1]);
        __half2 hi = __floats2half2_rn(tile[1][s][wp], tile[1][s][wp + 1]);
        uint2 u;
        u.x = *(const unsigned int*)&lo;
        u.y = *(const unsigned int*)&hi;
        g_qh[(dp * QW + wp) * NS + s] = u;
    }
}

// Kernel 2: 4 rays per CTA. Phase 0/1 cooperatively precompute per-sample
// (byte offset, 4 corner weights) into smem; phase 2 is a branch-free
// LDS + LDG.64 + 2-cvt + 4-FMA inner loop per slice.
__global__ void __launch_bounds__(256) k_radon(float* __restrict__ d_out) {
    __shared__ float4 s_w[RPB][92];   // corner weights (w00,w01,w10,w11)
    __shared__ int    s_o[RPB][92];   // byte offset into g_qh (row base)
    __shared__ float  s_prm[RPB][4];  // sth, cth, Cx, Cy
    __shared__ int    s_ilo[RPB], s_cnt[RPB];
    __shared__ float  s_red[8];

    int tid = threadIdx.x;

    // ---- Phase 0: per-ray params + analytic active range (4 threads) ----
    if (tid < RPB) {
        int ray = blockIdx.x * RPB + tid;
        int a   = ray / LL;
        int j   = ray - a * LL;
        float theta = (float)a * (float)(120.0 / 119.0 * 3.14159265358979323846 / 180.0);
        float cth, sth;
        sincosf(theta, &sth, &cth);
        float uj = (float)(j - 45);
        float Cx = fmaf(cth, uj, 32.0f) + 45.0f * sth;   // ix = Cx - sth*i
        float Cy = fmaf(sth, uj, 32.0f) - 45.0f * cth;   // iy = Cy + cth*i

        int ilo = 0, ihi = LL;
        {
            float D = -sth, C = Cx;
            if (fabsf(D) > 1e-6f) {
                float r1 = (-1.0f - C) / D, r2 = (64.0f - C) / D;
                float lo = fminf(r1, r2), hi = fmaxf(r1, r2);
                ilo = max(ilo, (int)ceilf(lo) - 1);
                ihi = min(ihi, (int)floorf(hi) + 2);
            } else if (C <= -1.0f || C >= 64.0f) ihi = ilo;
        }
        {
            float D = cth, C = Cy;
            if (fabsf(D) > 1e-6f) {
                float r1 = (-1.0f - C) / D, r2 = (64.0f - C) / D;
                float lo = fminf(r1, r2), hi = fmaxf(r1, r2);
                ilo = max(ilo, (int)ceilf(lo) - 1);
                ihi = min(ihi, (int)floorf(hi) + 2);
            } else if (C <= -1.0f || C >= 64.0f) ihi = ilo;
        }
        ilo = max(ilo, 0);
        ihi = min(ihi, LL);
        s_prm[tid][0] = sth; s_prm[tid][1] = cth;
        s_prm[tid][2] = Cx;  s_prm[tid][3] = Cy;
        s_ilo[tid] = ilo;
        s_cnt[tid] = max(ihi - ilo, 0);
    }
    __syncthreads();

    // ---- Phase 1: per-sample offsets + weights (cooperative, 4*91 entries) ----
    for (int t = tid; t < RPB * LL; t += 256) {
        int sub = t / LL;
        int ir  = t - sub * LL;
        if (ir < s_cnt[sub]) {
            int i = s_ilo[sub] + ir;
            float sth = s_prm[sub][0], cth = s_prm[sub][1];
            float Cx  = s_prm[sub][2], Cy  = s_prm[sub][3];
            float fi = (float)i;
            float ix = fmaf(-sth, fi, Cx);
            float iy = fmaf( cth, fi, Cy);
            float4 w = make_float4(0.f, 0.f, 0.f, 0.f);
            int off = 0;
            if (ix > -1.0f && ix < 64.0f && iy > -1.0f && iy < 64.0f) {
                float fw = floorf(ix), fd = floorf(iy);
                int   w0 = (int)fw,    d0 = (int)fd;    // in [-1, 63]
                float fx = ix - fw,    fy = iy - fd;
                float w11 = fx * fy;
                w.x = 1.0f - fx - fy + w11;   // (1-fx)(1-fy) -> v[dp][wp]
                w.y = fx - w11;               // fx(1-fy)     -> v[dp][wp+1]
                w.z = fy - w11;               // fy(1-fx)     -> v[dp+1][wp]
                w.w = w11;                    // fx*fy        -> v[dp+1][wp+1]
                off = ((d0 + 1) * QW + (w0 + 1)) * (NS * 8);  // byte offset (8B/elem)
            }
            s_w[sub][ir] = w;
            s_o[sub][ir] = off;
        }
    }
    __syncthreads();

    // ---- Phase 2: lean accumulate. 64 threads = slices of one ray. ----
    int s   = tid & 63;
    int sub = tid >> 6;
    int cnt = s_cnt[sub];
    const char* gq = (const char*)g_qh + s * 8;

    float acc0 = 0.0f, acc1 = 0.0f;
    #pragma unroll 4
    for (int k = 0; k < cnt; ++k) {
        float4 w = s_w[sub][k];                    // LDS.128 broadcast
        int off  = s_o[sub][k];
        uint2 u  = *(const uint2*)(gq + off);      // LDG.64 coalesced (256B/warp)
        float2 v01 = __half22float2(*(const __half2*)&u.x);
        float2 v23 = __half22float2(*(const __half2*)&u.y);
        acc0 = fmaf(w.x, v01.x, acc0);
        acc0 = fmaf(w.y, v01.y, acc0);
        acc1 = fmaf(w.z, v23.x, acc1);
        acc1 = fmaf(w.w, v23.y, acc1);
    }

    // Reduce |acc| within each 64-thread ray group, then across the CTA.
    float val = fabsf(acc0 + acc1);
    #pragma unroll
    for (int off = 16; off; off >>= 1)
        val += __shfl_down_sync(0xffffffffu, val, off);

    if ((tid & 31) == 0) s_red[tid >> 5] = val;
    __syncthreads();

    if (tid == 0) {
        double tot = 0.0;
        #pragma unroll
        for (int k = 0; k < 8; ++k) tot += (double)s_red[k];
        unsigned long long q = (unsigned long long)(tot * SCALE);
        atomicAdd(&g_total, q);
        __threadfence();
        unsigned int old = atomicAdd(&g_done, 1u);
        if (old == NBLK - 1) {
            unsigned long long total = atomicAdd(&g_total, 0ULL);  // fenced read
            d_out[0] = (float)((double)total * (1.0 / SCALE) / (double)NRAYS);
            g_total = 0ULL;   // reset for next graph replay
            g_done  = 0u;
        }
    }
}

extern "C" void kernel_launch(void* const* d_in, const int* in_sizes, int n_in,
                              void* d_out, int out_size) {
    const float* v_out = (const float*)d_in[0];
    const float* v_gt  = (const float*)d_in[1];

    k_build<<<QW, 256>>>(v_out, v_gt);
    k_radon<<<NBLK, 256>>>((float*)d_out);
}

// round 15
// speedup vs baseline: 2.4100x; 1.1363x over previous
#include <cuda_runtime.h>
#include <cuda_fp16.h>
#include <math.h>

#define NA 120            // angles
#define LL 91             // padded canvas size / detector bins
#define NS 64             // slices
#define QW 65             // quad-tap array extent per axis (dp,wp in [0,64])
#define NRAYS (NA * LL)   // 10920
#define RPB 8             // rays per CTA (one warp per ray)
#define NBLK  (NRAYS / RPB)   // 1365
#define MAXK 96           // per-ray sample slots, padded to multiple of 8
#define SCALE 4294967296.0    // 2^32 fixed-point scale

// Quad-tap array in fp16: g_qh[(dp*QW+wp)*NS+s] = half4(v[dp][wp], v[dp][wp+1],
// v[dp+1][wp], v[dp+1][wp+1]) packed as uint2 (8 bytes). v is the zero-padded
// transposed diff image (v[r][c] = diff(r-1, c-1)).
__device__ uint2 g_qh[QW * QW * NS];
// Fixed-point global accumulator + completion ticket (zero-initialized at load;
// the last k_radon CTA resets them, so graph replays stay correct).
__device__ unsigned long long g_total;
__device__ unsigned int g_done;

static __device__ __forceinline__ __half2 u2h(unsigned int u) {
    return *reinterpret_cast<__half2*>(&u);
}

// Kernel 1: fused diff + transpose + quad-tap build (fp16 output).
__global__ void __launch_bounds__(256) k_build(const float* __restrict__ a,
                                               const float* __restrict__ b) {
    __shared__ float tile[2][64][67];   // [plane][s][padded col]; cols 0,65 zero
    int dp = blockIdx.x;

    for (int k = threadIdx.x; k < 2 * 64 * 67; k += 256)
        ((float*)tile)[k] = 0.0f;
    __syncthreads();

    #pragma unroll
    for (int p = 0; p < 2; ++p) {
        int d = dp - 1 + p;
        if (d >= 0 && d < 64) {
            const float* pa = a + d * 4096;
            const float* pb = b + d * 4096;
            for (int k = threadIdx.x; k < 4096; k += 256)   // k = s*64 + w, coalesced
                tile[p][k >> 6][(k & 63) + 1] = pa[k] - pb[k];
        }
    }
    __syncthreads();

    for (int k = threadIdx.x; k < QW * NS; k += 256) {      // k = wp*64 + s
        int wp = k >> 6, s = k & 63;
        __half2 lo = __floats2half2_rn(tile[0][s][wp], tile[0][s][wp + 1]);
        __half2 hi = __floats2half2_rn(tile[1][s][wp], tile[1][s][wp + 1]);
        uint2 u;
        u.x = *(const unsigned int*)&lo;
        u.y = *(const unsigned int*)&hi;
        g_qh[(dp * QW + wp) * NS + s] = u;
    }
}

// Kernel 2: 8 rays per CTA, one warp per ray, each lane owns 2 slices.
// Phase 0/1 precompute per-sample packed meta (half2 weights + byte offset);
// phase 2: LDS.128 + LDG.128 + 4 HFMA2 per 2 slice-samples, branch-free.
__global__ void __launch_bounds__(256) k_radon(float* __restrict__ d_out) {
    __shared__ uint4  s_meta[RPB][MAXK]; // (w00w01 h2, w10w11 h2, byte off, 0)
    __shared__ float  s_prm[RPB][4];     // sth, cth, Cx, Cy
    __shared__ int    s_ilo[RPB], s_cnt[RPB], s_cntp[RPB];
    __shared__ float  s_red[RPB];

    int tid = threadIdx.x;

    // ---- Phase 0: per-ray params + analytic active range (8 threads) ----
    if (tid < RPB) {
        int ray = blockIdx.x * RPB + tid;
        int a   = ray / LL;
        int j   = ray - a * LL;
        float theta = (float)a * (float)(120.0 / 119.0 * 3.14159265358979323846 / 180.0);
        float cth, sth;
        sincosf(theta, &sth, &cth);
        float uj = (float)(j - 45);
        float Cx = fmaf(cth, uj, 32.0f) + 45.0f * sth;   // ix = Cx - sth*i
        float Cy = fmaf(sth, uj, 32.0f) - 45.0f * cth;   // iy = Cy + cth*i

        int ilo = 0, ihi = LL;
        {
            float D = -sth, C = Cx;
            if (fabsf(D) > 1e-6f) {
                float r1 = (-1.0f - C) / D, r2 = (64.0f - C) / D;
                float lo = fminf(r1, r2), hi = fmaxf(r1, r2);
                ilo = max(ilo, (int)ceilf(lo) - 1);
                ihi = min(ihi, (int)floorf(hi) + 2);
            } else if (C <= -1.0f || C >= 64.0f) ihi = ilo;
        }
        {
            float D = cth, C = Cy;
            if (fabsf(D) > 1e-6f) {
                float r1 = (-1.0f - C) / D, r2 = (64.0f - C) / D;
                float lo = fminf(r1, r2), hi = fmaxf(r1, r2);
                ilo = max(ilo, (int)ceilf(lo) - 1);
                ihi = min(ihi, (int)floorf(hi) + 2);
            } else if (C <= -1.0f || C >= 64.0f) ihi = ilo;
        }
        ilo = max(ilo, 0);
        ihi = min(ihi, LL);
        int cnt = max(ihi - ilo, 0);
        s_prm[tid][0] = sth; s_prm[tid][1] = cth;
        s_prm[tid][2] = Cx;  s_prm[tid][3] = Cy;
        s_ilo[tid]  = ilo;
        s_cnt[tid]  = cnt;
        s_cntp[tid] = (cnt + 7) & ~7;   // pad to multiple of 8 (<= 96)
    }
    __syncthreads();

    // ---- Phase 1: per-sample packed meta (8*96 = 768 entries) ----
    for (int t = tid; t < RPB * MAXK; t += 256) {
        int sub = t >> 7;          // MAXK = 96 < 128; use /MAXK semantics below
        sub = t / MAXK;
        int ir  = t - sub * MAXK;
        uint4 m = make_uint4(0u, 0u, 0u, 0u);
        if (ir < s_cnt[sub]) {
            int i = s_ilo[sub] + ir;
            float sth = s_prm[sub][0], cth = s_prm[sub][1];
            float Cx  = s_prm[sub][2], Cy  = s_prm[sub][3];
            float fi = (float)i;
            float ix = fmaf(-sth, fi, Cx);
            float iy = fmaf( cth, fi, Cy);
            if (ix > -1.0f && ix < 64.0f && iy > -1.0f && iy < 64.0f) {
                float fw = floorf(ix), fd = floorf(iy);
                int   w0 = (int)fw,    d0 = (int)fd;    // in [-1, 63]
                float fx = ix - fw,    fy = iy - fd;
                float w11 = fx * fy;
                float w00 = 1.0f - fx - fy + w11;
                float w01 = fx - w11;
                float w10 = fy - w11;
                __half2 lo = __floats2half2_rn(w00, w01);
                __half2 hi = __floats2half2_rn(w10, w11);
                m.x = *(const unsigned int*)&lo;
                m.y = *(const unsigned int*)&hi;
                m.z = (unsigned int)(((d0 + 1) * QW + (w0 + 1)) * (NS * 8));
            }
        }
        if (ir < MAXK) s_meta[sub][ir] = m;
    }
    __syncthreads();

    // ---- Phase 2: warp = ray, lane = slice pair (s = 2*lane, 2*lane+1) ----
    int lane = tid & 31;
    int sub  = tid >> 5;
    int cntp = s_cntp[sub];
    const char* base = (const char*)g_qh + lane * 16;

    float accA = 0.0f, accB = 0.0f;   // fp32 per-slice integrals
    for (int k0 = 0; k0 < cntp; k0 += 8) {
        __half2 z = __float2half2_rn(0.0f);
        __half2 h0 = z, h1 = z, h2 = z, h3 = z;
        #pragma unroll
        for (int k = 0; k < 8; ++k) {
            uint4 m = s_meta[sub][k0 + k];               // LDS.128 (warp-uniform)
            uint4 u = *(const uint4*)(base + m.z);       // LDG.128 coalesced
            h0 = __hfma2(u2h(m.x), u2h(u.x), h0);        // slice A: v00,v01
            h1 = __hfma2(u2h(m.y), u2h(u.y), h1);        // slice A: v10,v11
            h2 = __hfma2(u2h(m.x), u2h(u.z), h2);        // slice B: v00,v01
            h3 = __hfma2(u2h(m.y), u2h(u.w), h3);        // slice B: v10,v11
        }
        float2 f;
        f = __half22float2(h0); accA += f.x + f.y;
        f = __half22float2(h1); accA += f.x + f.y;
        f = __half22float2(h2); accB += f.x + f.y;
        f = __half22float2(h3); accB += f.x + f.y;
    }

    // |integral| per slice, reduce over the warp (= over 64 slices of the ray).
    float val = fabsf(accA) + fabsf(accB);
    #pragma unroll
    for (int off = 16; off; off >>= 1)
        val += __shfl_down_sync(0xffffffffu, val, off);

    if (lane == 0) s_red[sub] = val;
    __syncthreads();

    if (tid == 0) {
        double tot = 0.0;
        #pragma unroll
        for (int k = 0; k < RPB; ++k) tot += (double)s_red[k];
        unsigned long long q = (unsigned long long)(tot * SCALE);
        atomicAdd(&g_total, q);
        __threadfence();
        unsigned int old = atomicAdd(&g_done, 1u);
        if (old == NBLK - 1) {
            unsigned long long total = atomicAdd(&g_total, 0ULL);  // fenced read
            d_out[0] = (float)((double)total * (1.0 / SCALE) / (double)NRAYS);
            g_total = 0ULL;   // reset for next graph replay
            g_done  = 0u;
        }
    }
}

extern "C" void kernel_launch(void* const* d_in, const int* in_sizes, int n_in,
                              void* d_out, int out_size) {
    const float* v_out = (const float*)d_in[0];
    const float* v_gt  = (const float*)d_in[1];

    k_build<<<QW, 256>>>(v_out, v_gt);
    k_radon<<<NBLK, 256>>>((float*)d_out);
}